// round 14
// baseline (speedup 1.0000x reference)
#include <cuda_runtime.h>
#include <cuda_fp16.h>
#include <cstdint>

// ---------------- geometry constants (match reference) ----------------
#define VOL      256
#define N_PROJ   256
#define N_DET    384
#define N_SAMP   256
#define SID_F    400.0f
#define SDD_F    800.0f
#define DETSP    1.2f

#define TH_STEP  0.024543692442321777f   // 2*pi/256 in fp32
#define DT_F     1.4142135623730951f     // diag/N = sqrt(2)
#define INV_DT   0.7071067811865476f
#define T_BASE   218.98066401624382f     // SID - diag/2
#define T_END    581.0193359837562f      // SID + diag/2

#define MAGICF   12582912.0f             // 2^23 + 2^22

// Padded quad grid: cell i <-> corner coord c0 = i - 4, c0 in [-4, 259].
// Cells with c0 <= -2 or c0 >= 256 are all-zero, absorbing the <=2.83px
// interval-clipping slack without per-sample clamps.
#define QN       264
#define QSTRIDE  264
#define QPAD     4
#define QPERB    (QN * QSTRIDE)

// Batch-interleaved, basis-transformed fp16 cells (16B):
//   .x = a (mean), .y = b (minor-coef), .z = c (major-coef), .w = e (cross)
//   each as half2{batch0, batch1};  v = (a + b*w'm) + w'M*(c + e*w'm)
// Layout A: maj = y, min = x.   Layout B: maj = x, min = y.
__device__ uint4 g_qA[QPERB];
__device__ uint4 g_qB[QPERB];

// ---------------------------------------------------------------------
// Tiled prep: 32x32-cell tiles; pixels staged in smem, cells computed
// once, then BOTH layouts written with coalesced STG.128.
// Grid: 9x9 = 81 tiles (ceil(264/32) = 9), 256 threads.
// ---------------------------------------------------------------------
#define PTILE 32
#define NTILE 9

__global__ void fanproj_prep_kernel(const float* __restrict__ img)
{
    __shared__ float px[2][PTILE + 1][PTILE + 2];    // 33 x 34 (pad)
    __shared__ uint4 cells[PTILE][PTILE + 1];        // pad to 33 (conflict-free cols)

    int t   = threadIdx.x;                           // 0..255
    int tx  = blockIdx.x % NTILE;
    int ty  = blockIdx.x / NTILE;
    int bx0 = tx * PTILE;
    int by0 = ty * PTILE;

    // stage 33x33 pixels x 2 batches (zero outside image)
    for (int i = t; i < (PTILE + 1) * (PTILE + 1); i += 256) {
        int r = i / (PTILE + 1);
        int c = i - r * (PTILE + 1);
        int gy = by0 - QPAD + r;
        int gx = bx0 - QPAD + c;
        bool in = (gy >= 0) && (gy < VOL) && (gx >= 0) && (gx < VOL);
        px[0][r][c] = in ? img[gy * VOL + gx]             : 0.f;
        px[1][r][c] = in ? img[VOL * VOL + gy * VOL + gx] : 0.f;
    }
    __syncthreads();

    // compute 32x32 cells (A-format: .y = x-coef, .z = y-coef)
    for (int i = t; i < PTILE * PTILE; i += 256) {
        int cy = i >> 5;
        int cx = i & 31;
        float a[2], bx[2], cyc[2], e[2];
        #pragma unroll
        for (int b = 0; b < 2; ++b) {
            float v00 = px[b][cy][cx];
            float v01 = px[b][cy][cx + 1];
            float v10 = px[b][cy + 1][cx];
            float v11 = px[b][cy + 1][cx + 1];
            a[b]   = 0.25f * ((v00 + v01) + (v10 + v11));
            bx[b]  = 0.5f  * ((v01 - v00) + (v11 - v10));   // x-coef
            cyc[b] = 0.5f  * ((v10 - v00) + (v11 - v01));   // y-coef
            e[b]   = (v11 - v10) - (v01 - v00);             // cross
        }
        __half2 hA = __halves2half2(__float2half_rn(a[0]),   __float2half_rn(a[1]));
        __half2 hB = __halves2half2(__float2half_rn(bx[0]),  __float2half_rn(bx[1]));
        __half2 hC = __halves2half2(__float2half_rn(cyc[0]), __float2half_rn(cyc[1]));
        __half2 hE = __halves2half2(__float2half_rn(e[0]),   __float2half_rn(e[1]));
        uint4 cell;
        cell.x = *reinterpret_cast<uint32_t*>(&hA);
        cell.y = *reinterpret_cast<uint32_t*>(&hB);
        cell.z = *reinterpret_cast<uint32_t*>(&hC);
        cell.w = *reinterpret_cast<uint32_t*>(&hE);
        cells[cy][cx] = cell;
    }
    __syncthreads();

    // write layout A (rows = y): warp sweeps cx -> contiguous 512B stores
    for (int i = t; i < PTILE * PTILE; i += 256) {
        int cy = i >> 5;
        int cx = i & 31;
        int gy = by0 + cy;
        int gx = bx0 + cx;
        if (gy < QN && gx < QN)
            g_qA[gy * QSTRIDE + gx] = cells[cy][cx];
    }
    // write layout B (rows = x, b/c swapped): warp sweeps cy -> coalesced
    for (int i = t; i < PTILE * PTILE; i += 256) {
        int cx = i >> 5;
        int cy = i & 31;
        int gy = by0 + cy;
        int gx = bx0 + cx;
        if (gy < QN && gx < QN) {
            uint4 c4 = cells[cy][cx];
            uint4 cb = make_uint4(c4.x, c4.z, c4.y, c4.w);
            g_qB[gx * QSTRIDE + gy] = cb;
        }
    }
}

// ---------------------------------------------------------------------
// 128 threads/block = 4 warps; block covers 32 detectors x 1 angle.
// Warp w: detectors (w&1)*16 + 0..15, sample-half (w>>1).
// Lane = 16*j + i: detector i, sample parity j (s += 2).
// Inner loop: 8 LDG.128 in flight per thread (MLP=8); weights are
// RECOMPUTED after the loads. Reg cap 73 (7 blocks/SM).
// ---------------------------------------------------------------------
__global__ void __launch_bounds__(128, 7) fanproj_main_kernel(float* __restrict__ out)
{
    int tid  = threadIdx.x;
    int w    = tid >> 5;                 // warp 0..3
    int lane = tid & 31;
    int i16  = lane & 15;                // detector within 16-group
    int j    = lane >> 4;                // sample parity 0/1
    int half = w >> 1;                   // sample half 0/1

    int d = blockIdx.x * 32 + (w & 1) * 16 + i16;   // detector 0..383
    int p = blockIdx.y;                              // angle 0..255

    float theta = (float)p * TH_STEP;
    float sn, cs;
    sincosf(theta, &sn, &cs);

    float off = ((float)d - (float)(N_DET - 1) * 0.5f) * DETSP;

    float rx = SDD_F * cs - off * sn;
    float ry = SDD_F * sn + off * cs;
    float inv = rsqrtf(SDD_F * SDD_F + off * off);
    rx *= inv;
    ry *= inv;

    float cxp = fmaf(-SID_F, cs, 127.5f);
    float cyp = fmaf(-SID_F, sn, 127.5f);

    // ray/box interval: pixel coords in (-1, 256)
    float rxs = copysignf(fmaxf(fabsf(rx), 1e-10f), rx);
    float rys = copysignf(fmaxf(fabsf(ry), 1e-10f), ry);
    float ivx = 1.0f / rxs;
    float ivy = 1.0f / rys;
    float tx1 = (-1.0f  - cxp) * ivx;
    float tx2 = (256.0f - cxp) * ivx;
    float ty1 = (-1.0f  - cyp) * ivy;
    float ty2 = (256.0f - cyp) * ivy;
    float tlo = fmaxf(fmaxf(fminf(tx1, tx2), fminf(ty1, ty2)), T_BASE);
    float thi = fminf(fminf(fmaxf(tx1, tx2), fmaxf(ty1, ty2)), T_END);

    float slo = fmaf(tlo - T_BASE, INV_DT, -0.5f);
    float shi = fmaf(thi - T_BASE, INV_DT, -0.5f);
    int s0 = max(0,      __float2int_rd(slo) - 1);
    int s1 = min(N_SAMP, __float2int_ru(shi) + 2);
    int len = max(0, s1 - s0);

    int mid = s0 + (len >> 1);
    int a0 = half ? mid : s0;
    int a1 = half ? s1  : mid;

    // layout: minor coord = larger |u| component; u = (-sn, cs)
    bool useA = fabsf(sn) >= fabsf(cs);
    float rMin = useA ? rx : ry;
    float rMaj = useA ? ry : rx;
    float cMin = (useA ? cxp : cyp) + (float)QPAD;
    float cMaj = (useA ? cyp : cxp) + (float)QPAD;
    const uint4* __restrict__ quad = useA ? g_qA : g_qB;

    float drMin = rMin * DT_F * 2.0f;    // stride-2 sampling per parity lane
    float drMaj = rMaj * DT_F * 2.0f;
    // f(s) at s = a0 + j + 2k: base at fs0, step per k is 2*dt*r
    float fs0   = (float)(a0 + j) + 0.5f;
    float bMin  = fmaf(fs0, rMin * DT_F, fmaf(T_BASE, rMin, cMin)) - 0.5f;
    float bMaj  = fmaf(fs0, rMaj * DT_F, fmaf(T_BASE, rMaj, cMaj)) - 0.5f;

    // number of stride-2 iterations for this lane
    int n = max(0, (a1 - (a0 + j) + 1) >> 1);

    float acc0 = 0.f, acc1 = 0.f;
    float fkb = 0.0f;                    // chunk-base k as float

    // ---- chunked main loop: 8 loads in flight, weights recomputed ----
    while (n >= 8) {
        uint4 qv[8];
        #pragma unroll
        for (int k = 0; k < 8; ++k) {
            float fk = fkb + (float)k;
            float fM = fmaf(fk, drMaj, bMaj);
            float fm = fmaf(fk, drMin, bMin);
            int iM = (int)(__float_as_uint(fM + MAGICF) & 0x1FFu);
            int im = (int)(__float_as_uint(fm + MAGICF) & 0x1FFu);
            qv[k] = __ldg(quad + (iM * QSTRIDE + im));
        }
        #pragma unroll
        for (int k = 0; k < 8; ++k) {
            float fk = fkb + (float)k;
            float fM = fmaf(fk, drMaj, bMaj);
            float fm = fmaf(fk, drMin, bMin);
            float kM = fM + MAGICF;
            float km = fm + MAGICF;
            float wM = fM - (kM - MAGICF);   // w' in (-0.5, 0.5]
            float wm = fm - (km - MAGICF);
            __half2 A  = *reinterpret_cast<__half2*>(&qv[k].x);
            __half2 Bc = *reinterpret_cast<__half2*>(&qv[k].y);
            __half2 Cc = *reinterpret_cast<__half2*>(&qv[k].z);
            __half2 Ec = *reinterpret_cast<__half2*>(&qv[k].w);
            __half2 wm2 = __float2half2_rn(wm);
            __half2 wM2 = __float2half2_rn(wM);
            __half2 t0 = __hfma2(wm2, Bc, A);
            __half2 t1 = __hfma2(wm2, Ec, Cc);
            __half2 u  = __hfma2(wM2, t1, t0);
            acc0 += __low2float(u);
            acc1 += __high2float(u);
        }
        fkb += 8.0f;
        n -= 8;
    }
    // ---- tail ----
    while (n > 0) {
        float fM = fmaf(fkb, drMaj, bMaj);
        float fm = fmaf(fkb, drMin, bMin);
        fkb += 1.0f;
        float kM = fM + MAGICF;
        float km = fm + MAGICF;
        int iM = (int)(__float_as_uint(kM) & 0x1FFu);
        int im = (int)(__float_as_uint(km) & 0x1FFu);
        float wM = fM - (kM - MAGICF);
        float wm = fm - (km - MAGICF);
        uint4 q = __ldg(quad + (iM * QSTRIDE + im));
        __half2 A  = *reinterpret_cast<__half2*>(&q.x);
        __half2 Bc = *reinterpret_cast<__half2*>(&q.y);
        __half2 Cc = *reinterpret_cast<__half2*>(&q.z);
        __half2 Ec = *reinterpret_cast<__half2*>(&q.w);
        __half2 wm2 = __float2half2_rn(wm);
        __half2 wM2 = __float2half2_rn(wM);
        __half2 t0 = __hfma2(wm2, Bc, A);
        __half2 t1 = __hfma2(wm2, Ec, Cc);
        __half2 u  = __hfma2(wM2, t1, t0);
        acc0 += __low2float(u);
        acc1 += __high2float(u);
        --n;
    }

    // fold sample-parity pairs (lanes 16 apart share a detector & half)
    acc0 += __shfl_xor_sync(0xFFFFFFFFu, acc0, 16);
    acc1 += __shfl_xor_sync(0xFFFFFFFFu, acc1, 16);

    // fold the two halves across warps
    __shared__ float2 red[4][16];
    if (j == 0) red[w][i16] = make_float2(acc0, acc1);
    __syncthreads();
    if (tid < 32) {
        int D   = tid;            // detector within block
        int wlo = D >> 4;         // warp holding half 0 for this det group
        int ii  = D & 15;
        float2 rA = red[wlo][ii];
        float2 rB = red[wlo + 2][ii];
        int dg = blockIdx.x * 32 + D;
        out[p * N_DET + dg]                  = (rA.x + rB.x) * DT_F;  // batch 0
        out[N_PROJ * N_DET + p * N_DET + dg] = (rA.y + rB.y) * DT_F;  // batch 1
    }
}

// ---------------------------------------------------------------------
extern "C" void kernel_launch(void* const* d_in, const int* in_sizes, int n_in,
                              void* d_out, int out_size)
{
    const float* x = (const float*)d_in[0];
    float* out = (float*)d_out;

    fanproj_prep_kernel<<<NTILE * NTILE, 256>>>(x);

    dim3 grid(N_DET / 32, N_PROJ);
    fanproj_main_kernel<<<grid, 128>>>(out);
}

// round 15
// speedup vs baseline: 1.0738x; 1.0738x over previous
#include <cuda_runtime.h>
#include <cuda_fp16.h>
#include <cstdint>

// ---------------- geometry constants (match reference) ----------------
#define VOL      256
#define N_PROJ   256
#define N_DET    384
#define N_SAMP   256
#define SID_F    400.0f
#define SDD_F    800.0f
#define DETSP    1.2f

#define TH_STEP  0.024543692442321777f   // 2*pi/256 in fp32
#define DT_F     1.4142135623730951f     // diag/N = sqrt(2)
#define INV_DT   0.7071067811865476f
#define T_BASE   218.98066401624382f     // SID - diag/2
#define T_END    581.0193359837562f      // SID + diag/2

#define MAGICF   12582912.0f             // 2^23 + 2^22

// Padded quad grid: cell i <-> corner coord c0 = i - 4, c0 in [-4, 259].
// Cells with c0 <= -2 or c0 >= 256 are all-zero, absorbing the <=2.83px
// interval-clipping slack without per-sample clamps.
#define QN       264
#define QSTRIDE  264
#define QPAD     4
#define QPERB    (QN * QSTRIDE)

// Batch-interleaved, basis-transformed fp16 cells (16B):
//   .x = a (mean), .y = b (minor-coef), .z = c (major-coef), .w = e (cross)
//   each as half2{batch0, batch1};  v = (a + b*w'm) + w'M*(c + e*w'm)
// Layout A: maj = y, min = x.   Layout B: maj = x, min = y.
__device__ uint4 g_qA[QPERB];
__device__ uint4 g_qB[QPERB];

// ---------------------------------------------------------------------
__global__ void fanproj_prep_kernel(const float* __restrict__ img)
{
    int idx = blockIdx.x * blockDim.x + threadIdx.x;
    const int total = QN * QN;
    if (idx >= total) return;

    int iy = idx / QN;
    int ix = idx - iy * QN;
    int y0 = iy - QPAD;
    int x0 = ix - QPAD;

    float a[2], bx[2], cy[2], e[2];
    bool xa = (x0 >= 0)     && (x0 < VOL);
    bool xb = (x0 + 1 >= 0) && (x0 + 1 < VOL);
    bool ya = (y0 >= 0)     && (y0 < VOL);
    bool yb = (y0 + 1 >= 0) && (y0 + 1 < VOL);
    #pragma unroll
    for (int b = 0; b < 2; ++b) {
        const float* im = img + b * (VOL * VOL);
        float v00 = (ya && xa) ? im[y0 * VOL + x0]           : 0.f;
        float v01 = (ya && xb) ? im[y0 * VOL + x0 + 1]       : 0.f;
        float v10 = (yb && xa) ? im[(y0 + 1) * VOL + x0]     : 0.f;
        float v11 = (yb && xb) ? im[(y0 + 1) * VOL + x0 + 1] : 0.f;
        a[b]  = 0.25f * ((v00 + v01) + (v10 + v11));
        bx[b] = 0.5f  * ((v01 - v00) + (v11 - v10));   // x-coef
        cy[b] = 0.5f  * ((v10 - v00) + (v11 - v01));   // y-coef
        e[b]  = (v11 - v10) - (v01 - v00);             // cross
    }

    __half2 hA = __halves2half2(__float2half_rn(a[0]),  __float2half_rn(a[1]));
    __half2 hB = __halves2half2(__float2half_rn(bx[0]), __float2half_rn(bx[1]));
    __half2 hC = __halves2half2(__float2half_rn(cy[0]), __float2half_rn(cy[1]));
    __half2 hE = __halves2half2(__float2half_rn(e[0]),  __float2half_rn(e[1]));

    uint4 ca;   // layout A: minor = x
    ca.x = *reinterpret_cast<uint32_t*>(&hA);
    ca.y = *reinterpret_cast<uint32_t*>(&hB);
    ca.z = *reinterpret_cast<uint32_t*>(&hC);
    ca.w = *reinterpret_cast<uint32_t*>(&hE);
    g_qA[iy * QSTRIDE + ix] = ca;

    uint4 cb;   // layout B: minor = y
    cb.x = *reinterpret_cast<uint32_t*>(&hA);
    cb.y = *reinterpret_cast<uint32_t*>(&hC);
    cb.z = *reinterpret_cast<uint32_t*>(&hB);
    cb.w = *reinterpret_cast<uint32_t*>(&hE);
    g_qB[ix * QSTRIDE + iy] = cb;
}

// ---------------------------------------------------------------------
// 128 threads/block = 4 warps; block covers 16 detectors x 2 ADJACENT
// ANGLES (p, p+1) so all four warps walk nearly the same grid strip
// (cold L1/L2 lines fetched once, used twice).
// Warp w: angle-in-pair ja = w>>1, sample-half = w&1.
// Lane = 16*j + i: detector i, sample parity j (s += 2).
// Inner loop: 8 LDG.128 in flight per thread (MLP=8); weights are
// RECOMPUTED after the loads. Reg cap 73 (7 blocks/SM).
// ---------------------------------------------------------------------
__global__ void __launch_bounds__(128, 7) fanproj_main_kernel(float* __restrict__ out)
{
    int tid  = threadIdx.x;
    int w    = tid >> 5;                 // warp 0..3
    int lane = tid & 31;
    int i16  = lane & 15;                // detector within 16-group
    int j    = lane >> 4;                // sample parity 0/1
    int half = w & 1;                    // sample half 0/1
    int ja   = w >> 1;                   // angle within pair 0/1

    int d = blockIdx.x * 16 + i16;       // detector 0..383
    int p = blockIdx.y * 2 + ja;         // angle 0..255

    float theta = (float)p * TH_STEP;
    float sn, cs;
    sincosf(theta, &sn, &cs);

    float off = ((float)d - (float)(N_DET - 1) * 0.5f) * DETSP;

    float rx = SDD_F * cs - off * sn;
    float ry = SDD_F * sn + off * cs;
    float inv = rsqrtf(SDD_F * SDD_F + off * off);
    rx *= inv;
    ry *= inv;

    float cxp = fmaf(-SID_F, cs, 127.5f);
    float cyp = fmaf(-SID_F, sn, 127.5f);

    // ray/box interval: pixel coords in (-1, 256)
    float rxs = copysignf(fmaxf(fabsf(rx), 1e-10f), rx);
    float rys = copysignf(fmaxf(fabsf(ry), 1e-10f), ry);
    float ivx = 1.0f / rxs;
    float ivy = 1.0f / rys;
    float tx1 = (-1.0f  - cxp) * ivx;
    float tx2 = (256.0f - cxp) * ivx;
    float ty1 = (-1.0f  - cyp) * ivy;
    float ty2 = (256.0f - cyp) * ivy;
    float tlo = fmaxf(fmaxf(fminf(tx1, tx2), fminf(ty1, ty2)), T_BASE);
    float thi = fminf(fminf(fmaxf(tx1, tx2), fmaxf(ty1, ty2)), T_END);

    float slo = fmaf(tlo - T_BASE, INV_DT, -0.5f);
    float shi = fmaf(thi - T_BASE, INV_DT, -0.5f);
    int s0 = max(0,      __float2int_rd(slo) - 1);
    int s1 = min(N_SAMP, __float2int_ru(shi) + 2);
    int len = max(0, s1 - s0);

    int mid = s0 + (len >> 1);
    int a0 = half ? mid : s0;
    int a1 = half ? s1  : mid;

    // layout: minor coord = larger |u| component; u = (-sn, cs)
    bool useA = fabsf(sn) >= fabsf(cs);
    float rMin = useA ? rx : ry;
    float rMaj = useA ? ry : rx;
    float cMin = (useA ? cxp : cyp) + (float)QPAD;
    float cMaj = (useA ? cyp : cxp) + (float)QPAD;
    const uint4* __restrict__ quad = useA ? g_qA : g_qB;

    float drMin = rMin * DT_F * 2.0f;    // stride-2 sampling per parity lane
    float drMaj = rMaj * DT_F * 2.0f;
    // f(s) at s = a0 + j + 2k: base at fs0, step per k is 2*dt*r
    float fs0   = (float)(a0 + j) + 0.5f;
    float bMin  = fmaf(fs0, rMin * DT_F, fmaf(T_BASE, rMin, cMin)) - 0.5f;
    float bMaj  = fmaf(fs0, rMaj * DT_F, fmaf(T_BASE, rMaj, cMaj)) - 0.5f;

    // number of stride-2 iterations for this lane
    int n = max(0, (a1 - (a0 + j) + 1) >> 1);

    float acc0 = 0.f, acc1 = 0.f;
    float fkb = 0.0f;                    // chunk-base k as float

    // ---- chunked main loop: 8 loads in flight, weights recomputed ----
    while (n >= 8) {
        uint4 qv[8];
        #pragma unroll
        for (int k = 0; k < 8; ++k) {
            float fk = fkb + (float)k;
            float fM = fmaf(fk, drMaj, bMaj);
            float fm = fmaf(fk, drMin, bMin);
            int iM = (int)(__float_as_uint(fM + MAGICF) & 0x1FFu);
            int im = (int)(__float_as_uint(fm + MAGICF) & 0x1FFu);
            qv[k] = __ldg(quad + (iM * QSTRIDE + im));
        }
        #pragma unroll
        for (int k = 0; k < 8; ++k) {
            float fk = fkb + (float)k;
            float fM = fmaf(fk, drMaj, bMaj);
            float fm = fmaf(fk, drMin, bMin);
            float kM = fM + MAGICF;
            float km = fm + MAGICF;
            float wM = fM - (kM - MAGICF);   // w' in (-0.5, 0.5]
            float wm = fm - (km - MAGICF);
            __half2 A  = *reinterpret_cast<__half2*>(&qv[k].x);
            __half2 Bc = *reinterpret_cast<__half2*>(&qv[k].y);
            __half2 Cc = *reinterpret_cast<__half2*>(&qv[k].z);
            __half2 Ec = *reinterpret_cast<__half2*>(&qv[k].w);
            __half2 wm2 = __float2half2_rn(wm);
            __half2 wM2 = __float2half2_rn(wM);
            __half2 t0 = __hfma2(wm2, Bc, A);
            __half2 t1 = __hfma2(wm2, Ec, Cc);
            __half2 u  = __hfma2(wM2, t1, t0);
            acc0 += __low2float(u);
            acc1 += __high2float(u);
        }
        fkb += 8.0f;
        n -= 8;
    }
    // ---- tail ----
    while (n > 0) {
        float fM = fmaf(fkb, drMaj, bMaj);
        float fm = fmaf(fkb, drMin, bMin);
        fkb += 1.0f;
        float kM = fM + MAGICF;
        float km = fm + MAGICF;
        int iM = (int)(__float_as_uint(kM) & 0x1FFu);
        int im = (int)(__float_as_uint(km) & 0x1FFu);
        float wM = fM - (kM - MAGICF);
        float wm = fm - (km - MAGICF);
        uint4 q = __ldg(quad + (iM * QSTRIDE + im));
        __half2 A  = *reinterpret_cast<__half2*>(&q.x);
        __half2 Bc = *reinterpret_cast<__half2*>(&q.y);
        __half2 Cc = *reinterpret_cast<__half2*>(&q.z);
        __half2 Ec = *reinterpret_cast<__half2*>(&q.w);
        __half2 wm2 = __float2half2_rn(wm);
        __half2 wM2 = __float2half2_rn(wM);
        __half2 t0 = __hfma2(wm2, Bc, A);
        __half2 t1 = __hfma2(wm2, Ec, Cc);
        __half2 u  = __hfma2(wM2, t1, t0);
        acc0 += __low2float(u);
        acc1 += __high2float(u);
        --n;
    }

    // fold sample-parity pairs (lanes 16 apart share a detector/half/angle)
    acc0 += __shfl_xor_sync(0xFFFFFFFFu, acc0, 16);
    acc1 += __shfl_xor_sync(0xFFFFFFFFu, acc1, 16);

    // fold the two halves per angle across warps
    __shared__ float2 red[4][16];
    if (j == 0) red[w][i16] = make_float2(acc0, acc1);
    __syncthreads();
    if (tid < 32) {
        int jaO = tid >> 4;        // angle within pair
        int ii  = tid & 15;        // detector within group
        float2 rA = red[jaO * 2 + 0][ii];
        float2 rB = red[jaO * 2 + 1][ii];
        int pg = blockIdx.y * 2 + jaO;
        int dg = blockIdx.x * 16 + ii;
        out[pg * N_DET + dg]                  = (rA.x + rB.x) * DT_F;  // batch 0
        out[N_PROJ * N_DET + pg * N_DET + dg] = (rA.y + rB.y) * DT_F;  // batch 1
    }
}

// ---------------------------------------------------------------------
extern "C" void kernel_launch(void* const* d_in, const int* in_sizes, int n_in,
                              void* d_out, int out_size)
{
    const float* x = (const float*)d_in[0];
    float* out = (float*)d_out;

    const int prep_total = QN * QN;
    fanproj_prep_kernel<<<(prep_total + 255) / 256, 256>>>(x);

    dim3 grid(N_DET / 16, N_PROJ / 2);
    fanproj_main_kernel<<<grid, 128>>>(out);
}